// round 3
// baseline (speedup 1.0000x reference)
#include <cuda_runtime.h>

typedef unsigned long long u64;

#define S_ 512
#define B_ 64
#define H_ 1024
#define G_ 4096   // 4*H
#define NCTA_ 128

// Scratch (allocation-free rule: __device__ globals)
__device__ float g_gi[(size_t)S_ * (size_t)B_ * (size_t)G_];   // 512 MB
__device__ float g_y0T[(size_t)S_ * (size_t)H_ * (size_t)B_];  // 128 MB, layer-0 h transposed [t][h][b]
__device__ float g_ht[2 * (size_t)H_ * (size_t)B_];            // layer-1 h ping-pong [h][b]
__device__ unsigned g_barCnt = 0;
__device__ unsigned g_barGen = 0;

// ---- packed fp32x2 helpers (FFMA2 path) ----
__device__ __forceinline__ u64 pack_dup(float x) {
    u64 r; asm("mov.b64 %0, {%1, %1};" : "=l"(r) : "f"(x)); return r;
}
__device__ __forceinline__ void fma2(u64 &d, u64 a, u64 b) {
    asm("fma.rn.f32x2 %0, %1, %2, %0;" : "+l"(d) : "l"(a), "l"(b));
}
__device__ __forceinline__ float2 unpack2(u64 v) {
    float2 f; asm("mov.b64 {%0, %1}, %2;" : "=f"(f.x), "=f"(f.y) : "l"(v)); return f;
}
__device__ __forceinline__ float sigf(float x) { return 1.0f / (1.0f + __expf(-x)); }
__device__ __forceinline__ float tanhf_(float x) { return 2.0f / (1.0f + __expf(-2.0f * x)) - 1.0f; }

__device__ __forceinline__ void cpasync16(float* dst_smem, const float* src) {
    unsigned d = (unsigned)__cvta_generic_to_shared(dst_smem);
    asm volatile("cp.async.cg.shared.global [%0], [%1], 16;" :: "r"(d), "l"(src));
}

// Device-wide barrier (sense-reversing, 128 resident CTAs)
__device__ __forceinline__ void gsync() {
    __syncthreads();
    if (threadIdx.x == 0) {
        unsigned my = *(volatile unsigned*)&g_barGen;
        __threadfence();
        if (atomicAdd(&g_barCnt, 1) == NCTA_ - 1) {
            atomicExch(&g_barCnt, 0);
            __threadfence();
            atomicExch(&g_barGen, my + 1);
        } else {
            while (*(volatile unsigned*)&g_barGen == my) __nanosleep(64);
        }
        __threadfence();
    }
    __syncthreads();
}

// ============================================================================
// Input projection GEMM: GI[m,n] = dot(X[m,:], W[n,:]) + bih[n] + bhh[n]
// M=32768 (S*B), N=4096, K=1024.
// layer 0: A = x, [m][k] row-major (transpose-load into As[k][m]).
// layer 1: A = g_y0T, [t][k][b] -> direct [k][m] tile loads.
// Register double-buffer prefetch over k-tiles.
// ============================================================================
__global__ __launch_bounds__(256, 2) void gemm_gi(
    int layer, const float* __restrict__ Xin,
    const float* __restrict__ W,
    const float* __restrict__ bih, const float* __restrict__ bhh)
{
    __shared__ __align__(16) float As[16][128];
    __shared__ __align__(16) float Bs[16][128];
    float* GI = g_gi;
    const int K = H_;
    int bn = blockIdx.x, bm = blockIdx.y;
    int t = threadIdx.x;
    int tx = t & 15, ty = t >> 4;
    int lr = t >> 1;            // tile row (0..127) for transpose loads
    int lc = (t & 1) * 8;       // k-offset within 16-wide tile
    // layer-1 A chunk mapping: thread -> (k-within-tile, m-run of 8)
    int ck = t >> 4;            // 0..15
    int cm = (t & 15) * 8;      // 0..120

    const float* Ap = Xin + (size_t)(bm * 128 + lr) * K + lc;
    const float* Bp = W + (size_t)(bn * 128 + lr) * K + lc;

    u64 acc[8][4];
#pragma unroll
    for (int i = 0; i < 8; i++)
#pragma unroll
        for (int j = 0; j < 4; j++) acc[i][j] = 0ull;

    float4 ra0, ra1, rb0, rb1;
    // prologue loads (k0 = 0)
    if (layer == 0) {
        ra0 = *(const float4*)(Ap + 0);
        ra1 = *(const float4*)(Ap + 4);
    } else {
        size_t base = ((size_t)(bm * 2 + (cm >> 6)) * H_ + ck) * B_ + (cm & 63);
        ra0 = *(const float4*)(g_y0T + base);
        ra1 = *(const float4*)(g_y0T + base + 4);
    }
    rb0 = *(const float4*)(Bp + 0);
    rb1 = *(const float4*)(Bp + 4);

    for (int k0 = 0; k0 < K; k0 += 16) {
        // store current tile to smem
        if (layer == 0) {
            As[lc + 0][lr] = ra0.x; As[lc + 1][lr] = ra0.y; As[lc + 2][lr] = ra0.z; As[lc + 3][lr] = ra0.w;
            As[lc + 4][lr] = ra1.x; As[lc + 5][lr] = ra1.y; As[lc + 6][lr] = ra1.z; As[lc + 7][lr] = ra1.w;
        } else {
            *(float4*)&As[ck][cm] = ra0;
            *(float4*)&As[ck][cm + 4] = ra1;
        }
        Bs[lc + 0][lr] = rb0.x; Bs[lc + 1][lr] = rb0.y; Bs[lc + 2][lr] = rb0.z; Bs[lc + 3][lr] = rb0.w;
        Bs[lc + 4][lr] = rb1.x; Bs[lc + 5][lr] = rb1.y; Bs[lc + 6][lr] = rb1.z; Bs[lc + 7][lr] = rb1.w;
        __syncthreads();

        // prefetch next tile into registers (hidden under compute)
        if (k0 + 16 < K) {
            if (layer == 0) {
                ra0 = *(const float4*)(Ap + k0 + 16);
                ra1 = *(const float4*)(Ap + k0 + 20);
            } else {
                size_t base = ((size_t)(bm * 2 + (cm >> 6)) * H_ + (k0 + 16 + ck)) * B_ + (cm & 63);
                ra0 = *(const float4*)(g_y0T + base);
                ra1 = *(const float4*)(g_y0T + base + 4);
            }
            rb0 = *(const float4*)(Bp + k0 + 16);
            rb1 = *(const float4*)(Bp + k0 + 20);
        }

#pragma unroll
        for (int k = 0; k < 16; k++) {
            float4 av0 = *(const float4*)&As[k][ty * 8];
            float4 av1 = *(const float4*)&As[k][ty * 8 + 4];
            const ulonglong2* bp2 = (const ulonglong2*)&Bs[k][tx * 8];
            ulonglong2 bA = bp2[0], bB = bp2[1];
            float a_[8] = {av0.x, av0.y, av0.z, av0.w, av1.x, av1.y, av1.z, av1.w};
#pragma unroll
            for (int i = 0; i < 8; i++) {
                u64 ad = pack_dup(a_[i]);
                fma2(acc[i][0], ad, bA.x);
                fma2(acc[i][1], ad, bA.y);
                fma2(acc[i][2], ad, bB.x);
                fma2(acc[i][3], ad, bB.y);
            }
        }
        __syncthreads();
    }

    int row0 = bm * 128 + ty * 8, col0 = bn * 128 + tx * 8;
#pragma unroll
    for (int i = 0; i < 8; i++) {
#pragma unroll
        for (int jp = 0; jp < 4; jp++) {
            float2 v = unpack2(acc[i][jp]);
            int n0 = col0 + jp * 2;
            GI[(size_t)(row0 + i) * G_ + n0]     = v.x + bih[n0]     + bhh[n0];
            GI[(size_t)(row0 + i) * G_ + n0 + 1] = v.y + bih[n0 + 1] + bhh[n0 + 1];
        }
    }
}

// ============================================================================
// Persistent recurrent layer: 128 CTAs x 256 threads, ONE kernel for all 512
// timesteps, device-wide barrier between steps.
// CTA jb owns hidden indices [jb*8, jb*8+8) across all 4 gates (32 gate cols).
// W_hh slice (32 cols x 1024 k) resident in SMEM for the whole kernel.
// h is stored transposed [h][b]; tiles streamed via cp.async.cg (3-stage).
// c-state lives in registers (2 per thread) for the whole sequence.
// ============================================================================
#define WSM_F (32 * 1028)          // padded stride 1028
#define HS_F  (3 * 32 * B_)        // 3 tile buffers of [32 k][64 b]
#define GSM_F (B_ * 33)            // padded stride 33
#define SMEM_STEP ((WSM_F + HS_F + GSM_F) * 4)

__global__ __launch_bounds__(256) void lstm_layer(
    int layer, const float* __restrict__ whh,
    float* __restrict__ y1, float* __restrict__ hn_base, float* __restrict__ cn_base)
{
    extern __shared__ float sm[];
    float* Wsm = sm;                  // [32 cols][1028]
    float* Hs  = sm + WSM_F;          // 3 x [32][64]
    float* gsm = sm + WSM_F + HS_F;   // [64][33]

    const size_t BH = (size_t)B_ * H_;
    int tid = threadIdx.x;
    int tx = tid & 31;                // gate column within CTA
    int wy = tid >> 5;                // warp -> batch group (8 batches)
    int jb = blockIdx.x * 8;
    int n  = ((tx >> 3) * H_) + jb + (tx & 7);   // global gate column

    // ---- load W_hh slice into SMEM once (col-major-in-k, padded) ----
#pragma unroll 4
    for (int c = 0; c < 32; c++) {
        int wn = ((c >> 3) * H_) + jb + (c & 7);
        float4 v = *(const float4*)(whh + (size_t)wn * H_ + tid * 4);
        *(float4*)&Wsm[c * 1028 + tid * 4] = v;
    }
    __syncthreads();

    // cell-update mapping: thread -> (batch cb, j-offsets cj and cj+4)
    int cb = tid & 63;
    int cj = tid >> 6;
    float cs0 = 0.0f, cs1 = 0.0f;     // persistent cell state in registers

    int kr   = tid >> 4;              // h-tile loader row (0..15)
    int boff = (tid & 15) * 4;        // h-tile loader byte-run

    for (int t = 0; t < S_; t++) {
        const float* gi_t = g_gi + (size_t)t * B_ * G_;
        // early gi loads (independent of GEMM -> hidden under it)
        float gir[8];
#pragma unroll
        for (int p = 0; p < 4; p++) {
            int b0 = wy * 8 + 2 * p;
            gir[2 * p]     = gi_t[(size_t)b0 * G_ + n];
            gir[2 * p + 1] = gi_t[(size_t)(b0 + 1) * G_ + n];
        }

        u64 acc[4] = {0ull, 0ull, 0ull, 0ull};
        if (t > 0) {
            const float* hsrc = (layer == 0)
                ? (g_y0T + (size_t)(t - 1) * BH)
                : (g_ht + (size_t)((t - 1) & 1) * BH);
            // prefetch tile 0
            cpasync16(&Hs[kr * 64 + boff],        hsrc + (size_t)kr * 64 + boff);
            cpasync16(&Hs[(kr + 16) * 64 + boff], hsrc + (size_t)(kr + 16) * 64 + boff);
            asm volatile("cp.async.commit_group;");

            for (int kt = 0; kt < 32; kt++) {
                if (kt + 1 < 32) {
                    float* hb = &Hs[((kt + 1) % 3) * (32 * B_)];
                    size_t kbase = (size_t)(kt + 1) * 32;
                    cpasync16(hb + kr * 64 + boff,        hsrc + (kbase + kr) * 64 + boff);
                    cpasync16(hb + (kr + 16) * 64 + boff, hsrc + (kbase + kr + 16) * 64 + boff);
                    asm volatile("cp.async.commit_group;");
                    asm volatile("cp.async.wait_group 1;");
                } else {
                    asm volatile("cp.async.wait_group 0;");
                }
                __syncthreads();

                const float* hb = &Hs[(kt % 3) * (32 * B_)];
                const float* wp = &Wsm[tx * 1028 + kt * 32];
#pragma unroll
                for (int k4 = 0; k4 < 32; k4 += 4) {
                    float4 w4 = *(const float4*)(wp + k4);
#pragma unroll
                    for (int kk = 0; kk < 4; kk++) {
                        u64 wd = pack_dup((&w4.x)[kk]);
                        const ulonglong2* hp = (const ulonglong2*)(hb + (k4 + kk) * 64 + wy * 8);
                        ulonglong2 hA = hp[0];
                        ulonglong2 hB = hp[1];
                        fma2(acc[0], hA.x, wd);
                        fma2(acc[1], hA.y, wd);
                        fma2(acc[2], hB.x, wd);
                        fma2(acc[3], hB.y, wd);
                    }
                }
            }
        }

        // gates -> smem (+ input projection)
#pragma unroll
        for (int p = 0; p < 4; p++) {
            float2 v = unpack2(acc[p]);
            int b0 = wy * 8 + 2 * p;
            gsm[b0 * 33 + tx]       = v.x + gir[2 * p];
            gsm[(b0 + 1) * 33 + tx] = v.y + gir[2 * p + 1];
        }
        __syncthreads();

        // cell update (2 cells per thread), write h transposed [h][b]
        float* hdst = (layer == 0) ? (g_y0T + (size_t)t * BH)
                                   : (g_ht + (size_t)(t & 1) * BH);
        {
            float zi = gsm[cb * 33 + cj];
            float zf = gsm[cb * 33 + 8 + cj];
            float zg = gsm[cb * 33 + 16 + cj];
            float zo = gsm[cb * 33 + 24 + cj];
            cs0 = sigf(zf) * cs0 + sigf(zi) * tanhf_(zg);
            float h0v = sigf(zo) * tanhf_(cs0);

            float zi2 = gsm[cb * 33 + 4 + cj];
            float zf2 = gsm[cb * 33 + 12 + cj];
            float zg2 = gsm[cb * 33 + 20 + cj];
            float zo2 = gsm[cb * 33 + 28 + cj];
            cs1 = sigf(zf2) * cs1 + sigf(zi2) * tanhf_(zg2);
            float h1v = sigf(zo2) * tanhf_(cs1);

            hdst[(jb + cj) * 64 + cb]     = h0v;
            hdst[(jb + cj + 4) * 64 + cb] = h1v;
            if (layer == 1) {
                y1[((size_t)t * 64 + cb) * H_ + jb + cj]     = h0v;
                y1[((size_t)t * 64 + cb) * H_ + jb + cj + 4] = h1v;
            }
            if (t == S_ - 1) {
                size_t o = (size_t)layer * BH + (size_t)cb * H_ + jb + cj;
                hn_base[o]     = h0v;
                hn_base[o + 4] = h1v;
                cn_base[o]     = cs0;
                cn_base[o + 4] = cs1;
            }
        }
        gsync();
    }
}

// ============================================================================
// kernel_launch: 4 graph nodes total.
// Output layout: y1 [S,B,H] | h_n [2,B,H] | c_n [2,B,H]
// ============================================================================
extern "C" void kernel_launch(void* const* d_in, const int* in_sizes, int n_in,
                              void* d_out, int out_size)
{
    const float* x     = (const float*)d_in[0];
    const float* w_ih0 = (const float*)d_in[1];
    const float* w_hh0 = (const float*)d_in[2];
    const float* b_ih0 = (const float*)d_in[3];
    const float* b_hh0 = (const float*)d_in[4];
    const float* w_ih1 = (const float*)d_in[5];
    const float* w_hh1 = (const float*)d_in[6];
    const float* b_ih1 = (const float*)d_in[7];
    const float* b_hh1 = (const float*)d_in[8];

    float* y1 = (float*)d_out;
    float* hn = y1 + (size_t)S_ * B_ * H_;
    float* cn = hn + 2 * (size_t)B_ * H_;

    cudaFuncSetAttribute(lstm_layer, cudaFuncAttributeMaxDynamicSharedMemorySize, SMEM_STEP);

    dim3 ggrid(G_ / 128, (S_ * B_) / 128);  // (32, 256)

    gemm_gi<<<ggrid, 256>>>(0, x, w_ih0, b_ih0, b_hh0);
    lstm_layer<<<NCTA_, 256, SMEM_STEP>>>(0, w_hh0, y1, hn, cn);
    gemm_gi<<<ggrid, 256>>>(1, x, w_ih1, b_ih1, b_hh1);
    lstm_layer<<<NCTA_, 256, SMEM_STEP>>>(1, w_hh1, y1, hn, cn);
}